// round 12
// baseline (speedup 1.0000x reference)
#include <cuda_runtime.h>
#include <cuda_fp16.h>
#include <stdint.h>

#define BB 4
#define CC 512
#define NN 4096   // H*W
#define DD 512
#define SCALE 0.04419417382415922f   // 1/sqrt(512)

// Scratch (__device__ globals; no allocation allowed)
__device__ __half g_Xth[(size_t)BB * NN * CC];   // x transposed, fp16: [b][t][c]
__device__ __half g_Qh [(size_t)BB * NN * DD];   // [b][t][d]
__device__ __half g_Kh [(size_t)BB * NN * DD];   // [b][t][d]
__device__ __half g_Vth[(size_t)BB * DD * NN];   // [b][d][t] (V transposed)
__device__ __half g_Wqh[(size_t)DD * CC];
__device__ __half g_Wkh[(size_t)DD * CC];
__device__ __half g_Wvh[(size_t)DD * CC];
__device__ float  g_S  [(size_t)BB * NN * NN];   // f32 scores
__device__ __half g_Sh [(size_t)BB * NN * NN];   // fp16 probs for O GEMM

// ---------------------------------------------------------------------------
__device__ __forceinline__ uint32_t smem_u32(const void* p) {
    uint32_t a;
    asm("{ .reg .u64 t; cvta.to.shared.u64 t, %1; cvt.u32.u64 %0, t; }"
        : "=r"(a) : "l"(p));
    return a;
}

__device__ __forceinline__ void mma_f16(float c[4],
    uint32_t a0, uint32_t a1, uint32_t a2, uint32_t a3,
    uint32_t b0, uint32_t b1)
{
    asm volatile(
        "mma.sync.aligned.m16n8k16.row.col.f32.f16.f16.f32 "
        "{%0,%1,%2,%3}, {%4,%5,%6,%7}, {%8,%9}, {%0,%1,%2,%3};\n"
        : "+f"(c[0]), "+f"(c[1]), "+f"(c[2]), "+f"(c[3])
        : "r"(a0), "r"(a1), "r"(a2), "r"(a3), "r"(b0), "r"(b1));
}

__device__ __forceinline__ void ldsm_x4(uint32_t& r0, uint32_t& r1,
                                        uint32_t& r2, uint32_t& r3, uint32_t addr)
{
    asm volatile("ldmatrix.sync.aligned.m8n8.x4.shared.b16 {%0,%1,%2,%3}, [%4];"
        : "=r"(r0), "=r"(r1), "=r"(r2), "=r"(r3) : "r"(addr));
}

// ---------------------------------------------------------------------------
// fp16 GEMM: C[m][n] = scale * sum_k A[m][k] * B[n][k]   (A,B fp16; acc fp32)
// CTA 128(m) x 256(n), k-tile 32, 8 warps (2m x 4n), warp tile 64x64.
// 4-stage cp.async pipeline (3 in flight), ldmatrix fragment loads,
// 1 CTA/SM (acc-register ILP hides latency; CUTLASS-style shape).
// Smem row stride 80B: LDSM 8-row phases hit words {20r mod 32} = all banks.
// ---------------------------------------------------------------------------
#define TM 128
#define TN 256
#define KT 32
#define NST 4
#define ROWB 80                         // bytes per smem row (40 halfs)
#define A_BYTES (TM * ROWB)             // 10240
#define B_BYTES (TN * ROWB)             // 20480
#define STAGE   (A_BYTES + B_BYTES)     // 30720
#define GSMEM   (NST * STAGE)           // 122880

__device__ __forceinline__ void load_tile(uint32_t sst, const __half* __restrict__ Ab,
                                          const __half* __restrict__ Bb,
                                          int K, int ko, int tid)
{
    #pragma unroll
    for (int j = 0; j < 2; j++) {       // A: 128 rows x 4 uint4
        int i = tid + j * 256, row = i >> 2, q = i & 3;
        uint32_t dst = sst + row * ROWB + q * 16;
        const __half* src = Ab + (size_t)row * K + ko + q * 8;
        asm volatile("cp.async.cg.shared.global [%0], [%1], 16;\n" :: "r"(dst), "l"(src));
    }
    #pragma unroll
    for (int j = 0; j < 4; j++) {       // B: 256 rows x 4 uint4
        int i = tid + j * 256, row = i >> 2, q = i & 3;
        uint32_t dst = sst + A_BYTES + row * ROWB + q * 16;
        const __half* src = Bb + (size_t)row * K + ko + q * 8;
        asm volatile("cp.async.cg.shared.global [%0], [%1], 16;\n" :: "r"(dst), "l"(src));
    }
    asm volatile("cp.async.commit_group;\n");
}

template <bool HALF_OUT>
__global__ __launch_bounds__(256, 1) void gemm_h2(
    const __half* __restrict__ A, const __half* __restrict__ B, void* __restrict__ Cv,
    int Nglob, int K, size_t sA, size_t sB, size_t sC, float scale)
{
    extern __shared__ char sm[];
    uint32_t sbase = smem_u32(sm);
    int tid = threadIdx.x, lane = tid & 31, warp = tid >> 5;
    int r = lane >> 2, c = lane & 3;
    int wm = (warp >> 2) * 64;          // 0,64       (warp tile 64m x 64n)
    int wn = (warp & 3) * 64;           // 0,64,128,192

    const __half* Ab = A + blockIdx.z * sA + (size_t)(blockIdx.y * TM) * K;
    const __half* Bb = B + blockIdx.z * sB + (size_t)(blockIdx.x * TN) * K;
    int m0 = blockIdx.y * TM, n0 = blockIdx.x * TN;

    float acc[4][8][4] = {};            // [m-atom(16)][n-atom(8)][frag]

    // ldmatrix per-lane address components (within a stage)
    uint32_t a_off = (uint32_t)(wm + (lane & 15)) * ROWB + (lane >> 4) * 16;
    uint32_t b_off = A_BYTES
                   + (uint32_t)(wn + ((lane >> 4) * 8) + (lane & 7)) * ROWB
                   + ((lane >> 3) & 1) * 16;

    int nk = K / KT;
    load_tile(sbase + 0 * STAGE, Ab, Bb, K, 0 * KT, tid);
    load_tile(sbase + 1 * STAGE, Ab, Bb, K, 1 * KT, tid);
    load_tile(sbase + 2 * STAGE, Ab, Bb, K, 2 * KT, tid);

    for (int kt = 0; kt < nk; kt++) {
        int rem = nk - 1 - kt;
        if (rem >= 2)      asm volatile("cp.async.wait_group 2;\n" ::: "memory");
        else if (rem == 1) asm volatile("cp.async.wait_group 1;\n" ::: "memory");
        else               asm volatile("cp.async.wait_group 0;\n" ::: "memory");
        __syncthreads();

        if (kt + 3 < nk)
            load_tile(sbase + ((kt + 3) % NST) * STAGE, Ab, Bb, K, (kt + 3) * KT, tid);

        uint32_t st = sbase + (kt % NST) * STAGE;

        #pragma unroll
        for (int kk = 0; kk < 2; kk++) {
            uint32_t af[4][4], bf[8][2];
            uint32_t ab = st + a_off + kk * 32;
            #pragma unroll
            for (int ma = 0; ma < 4; ma++)
                ldsm_x4(af[ma][0], af[ma][1], af[ma][2], af[ma][3],
                        ab + ma * 16 * ROWB);
            uint32_t bb = st + b_off + kk * 32;
            #pragma unroll
            for (int p = 0; p < 4; p++)
                ldsm_x4(bf[2 * p][0], bf[2 * p][1], bf[2 * p + 1][0], bf[2 * p + 1][1],
                        bb + p * 16 * ROWB);
            #pragma unroll
            for (int ma = 0; ma < 4; ma++)
                #pragma unroll
                for (int na = 0; na < 8; na++)
                    mma_f16(acc[ma][na],
                            af[ma][0], af[ma][1], af[ma][2], af[ma][3],
                            bf[na][0], bf[na][1]);
        }
    }

    int cc = c * 2;
    #pragma unroll
    for (int ma = 0; ma < 4; ma++)
        #pragma unroll
        for (int na = 0; na < 8; na++) {
            int row = m0 + wm + ma * 16 + r;
            int col = n0 + wn + na * 8 + cc;
            float v0 = acc[ma][na][0] * scale, v1 = acc[ma][na][1] * scale;
            float v2 = acc[ma][na][2] * scale, v3 = acc[ma][na][3] * scale;
            if (HALF_OUT) {
                __half* Cb = (__half*)Cv + blockIdx.z * sC;
                *(__half2*)&Cb[(size_t)row * Nglob + col]       = __floats2half2_rn(v0, v1);
                *(__half2*)&Cb[(size_t)(row + 8) * Nglob + col] = __floats2half2_rn(v2, v3);
            } else {
                float* Cb = (float*)Cv + blockIdx.z * sC;
                *(float2*)&Cb[(size_t)row * Nglob + col]       = make_float2(v0, v1);
                *(float2*)&Cb[(size_t)(row + 8) * Nglob + col] = make_float2(v2, v3);
            }
        }
}

// ---------------------------------------------------------------------------
// x (B,C,N) f32 -> Xt (B,N,C) fp16
// ---------------------------------------------------------------------------
__global__ __launch_bounds__(256) void transpose_x(const float* __restrict__ x)
{
    __shared__ float tile[32][33];
    int b  = blockIdx.z;
    int t0 = blockIdx.x * 32;
    int c0 = blockIdx.y * 32;
    const float* in = x + (size_t)b * CC * NN;
    __half* out = g_Xth + (size_t)b * NN * CC;

    #pragma unroll
    for (int i = threadIdx.y; i < 32; i += 8)
        tile[i][threadIdx.x] = in[(size_t)(c0 + i) * NN + t0 + threadIdx.x];
    __syncthreads();
    #pragma unroll
    for (int i = threadIdx.y; i < 32; i += 8)
        out[(size_t)(t0 + i) * CC + c0 + threadIdx.x] = __float2half_rn(tile[threadIdx.x][i]);
}

__global__ __launch_bounds__(256) void conv_w(const float* __restrict__ Wq,
                                              const float* __restrict__ Wk,
                                              const float* __restrict__ Wv)
{
    int i = blockIdx.x * 256 + threadIdx.x;
    if (i < DD * CC) {
        g_Wqh[i] = __float2half_rn(Wq[i]);
        g_Wkh[i] = __float2half_rn(Wk[i]);
        g_Wvh[i] = __float2half_rn(Wv[i]);
    }
}

// ---------------------------------------------------------------------------
// Row softmax: read f32 S, write fp16 probs to g_Sh
// ---------------------------------------------------------------------------
__global__ __launch_bounds__(256) void softmax_kernel()
{
    __shared__ float red[256];
    size_t base = ((size_t)blockIdx.y * NN + blockIdx.x) * NN;
    const float* row = g_S + base;
    __half* rowh = g_Sh + base;
    int t = threadIdx.x;

    float vals[16];
    float m = -1e30f;
    #pragma unroll
    for (int u = 0; u < 16; u++) {
        vals[u] = row[t + u * 256];
        m = fmaxf(m, vals[u]);
    }
    red[t] = m;
    __syncthreads();
    for (int s = 128; s > 0; s >>= 1) {
        if (t < s) red[t] = fmaxf(red[t], red[t + s]);
        __syncthreads();
    }
    m = red[0];
    __syncthreads();

    float sum = 0.f;
    #pragma unroll
    for (int u = 0; u < 16; u++) {
        vals[u] = __expf(vals[u] - m);
        sum += vals[u];
    }
    red[t] = sum;
    __syncthreads();
    for (int s = 128; s > 0; s >>= 1) {
        if (t < s) red[t] += red[t + s];
        __syncthreads();
    }
    float inv = 1.0f / red[0];
    #pragma unroll
    for (int u = 0; u < 16; u++)
        rowh[t + u * 256] = __float2half_rn(vals[u] * inv);
}

// ---------------------------------------------------------------------------
// scores_out[b][j] = sum_i P[b][i][j] from fp16 probs
// ---------------------------------------------------------------------------
__global__ __launch_bounds__(256) void zero_scores(float* __restrict__ scores_out)
{
    int idx = blockIdx.x * 256 + threadIdx.x;
    if (idx < BB * NN) scores_out[idx] = 0.f;
}

__global__ __launch_bounds__(256) void colsum_kernel(float* __restrict__ scores_out)
{
    int b = blockIdx.z;
    int j = blockIdx.x * 256 + threadIdx.x;
    int i0 = blockIdx.y * 256;
    const __half* Sb = g_Sh + (size_t)b * NN * NN;
    float s = 0.f;
    #pragma unroll 8
    for (int i = i0; i < i0 + 256; i++)
        s += __half2float(Sb[(size_t)i * NN + j]);
    atomicAdd(&scores_out[(size_t)b * NN + j], s);
}

// ---------------------------------------------------------------------------
extern "C" void kernel_launch(void* const* d_in, const int* in_sizes, int n_in,
                              void* d_out, int out_size)
{
    const float* x  = (const float*)d_in[0];
    const float* Wk = (const float*)d_in[1];
    const float* Wq = (const float*)d_in[2];
    const float* Wv = (const float*)d_in[3];

    float* out        = (float*)d_out;                 // (B, D, H, W) = [b][d][t]
    float* scores_out = out + (size_t)BB * DD * NN;    // (B, 1, H, W)

    __half *Xt, *Q, *K, *Vt, *Sh, *Wqh, *Wkh, *Wvh;
    float *S;
    cudaGetSymbolAddress((void**)&Xt,  g_Xth);
    cudaGetSymbolAddress((void**)&Q,   g_Qh);
    cudaGetSymbolAddress((void**)&K,   g_Kh);
    cudaGetSymbolAddress((void**)&Vt,  g_Vth);
    cudaGetSymbolAddress((void**)&S,   g_S);
    cudaGetSymbolAddress((void**)&Sh,  g_Sh);
    cudaGetSymbolAddress((void**)&Wqh, g_Wqh);
    cudaGetSymbolAddress((void**)&Wkh, g_Wkh);
    cudaGetSymbolAddress((void**)&Wvh, g_Wvh);

    cudaFuncSetAttribute(gemm_h2<true>,  cudaFuncAttributeMaxDynamicSharedMemorySize, GSMEM);
    cudaFuncSetAttribute(gemm_h2<false>, cudaFuncAttributeMaxDynamicSharedMemorySize, GSMEM);

    // 0) fp16 operand prep
    conv_w<<<(DD * CC + 255) / 256, 256>>>(Wq, Wk, Wv);
    transpose_x<<<dim3(NN / 32, CC / 32, BB), dim3(32, 8)>>>(x);

    // 1) Q[t][d] = Xt . Wq^T
    gemm_h2<true><<<dim3(DD / TN, NN / TM, BB), 256, GSMEM>>>(
        Xt, Wqh, Q, DD, CC, (size_t)NN * CC, 0, (size_t)NN * DD, 1.0f);
    // 2) K[t][d] = Xt . Wk^T
    gemm_h2<true><<<dim3(DD / TN, NN / TM, BB), 256, GSMEM>>>(
        Xt, Wkh, K, DD, CC, (size_t)NN * CC, 0, (size_t)NN * DD, 1.0f);
    // 3) Vt[d][t] = Wv . Xt^T
    gemm_h2<true><<<dim3(NN / TN, DD / TM, BB), 256, GSMEM>>>(
        Wvh, Xt, Vt, NN, CC, 0, (size_t)NN * CC, (size_t)DD * NN, 1.0f);

    // 4) S[i][j] = SCALE * Q . K^T   (f32 out)
    gemm_h2<false><<<dim3(NN / TN, NN / TM, BB), 256, GSMEM>>>(
        Q, K, S, NN, DD, (size_t)NN * DD, (size_t)NN * DD, (size_t)NN * NN, SCALE);

    // 5) softmax rows -> fp16 probs
    softmax_kernel<<<dim3(NN, BB), 256>>>();

    // 6) out[d][t] = Vt . P^T  (f32 out, d-major layout directly)
    gemm_h2<false><<<dim3(NN / TN, DD / TM, BB), 256, GSMEM>>>(
        Vt, Sh, out, NN, NN, (size_t)DD * NN, (size_t)NN * NN, (size_t)DD * NN, 1.0f);

    // 7) scores_out[b][j] = sum_i P[b][i][j]
    zero_scores<<<(BB * NN + 255) / 256, 256>>>(scores_out);
    colsum_kernel<<<dim3(NN / 256, NN / 256, BB), 256>>>(scores_out);
}

// round 13
// speedup vs baseline: 1.0035x; 1.0035x over previous
#include <cuda_runtime.h>
#include <cuda_fp16.h>
#include <stdint.h>

#define BB 4
#define CC 512
#define NN 4096   // H*W
#define DD 512
#define SCALE 0.04419417382415922f   // 1/sqrt(512)

// Scratch (__device__ globals; no allocation allowed)
__device__ __half g_Xth[(size_t)BB * NN * CC];   // x transposed, fp16: [b][t][c]
__device__ __half g_Qh [(size_t)BB * NN * DD];   // [b][t][d]
__device__ __half g_Kh [(size_t)BB * NN * DD];   // [b][t][d]
__device__ __half g_Vth[(size_t)BB * DD * NN];   // [b][d][t] (V transposed)
__device__ __half g_Wqh[(size_t)DD * CC];
__device__ __half g_Wkh[(size_t)DD * CC];
__device__ __half g_Wvh[(size_t)DD * CC];
__device__ float  g_S  [(size_t)BB * NN * NN];   // f32 scores
__device__ __half g_Sh [(size_t)BB * NN * NN];   // fp16 probs for O GEMM

// ---------------------------------------------------------------------------
__device__ __forceinline__ uint32_t smem_u32(const void* p) {
    uint32_t a;
    asm("{ .reg .u64 t; cvta.to.shared.u64 t, %1; cvt.u32.u64 %0, t; }"
        : "=r"(a) : "l"(p));
    return a;
}

__device__ __forceinline__ void mma_f16(float c[4],
    uint32_t a0, uint32_t a1, uint32_t a2, uint32_t a3,
    uint32_t b0, uint32_t b1)
{
    asm volatile(
        "mma.sync.aligned.m16n8k16.row.col.f32.f16.f16.f32 "
        "{%0,%1,%2,%3}, {%4,%5,%6,%7}, {%8,%9}, {%0,%1,%2,%3};\n"
        : "+f"(c[0]), "+f"(c[1]), "+f"(c[2]), "+f"(c[3])
        : "r"(a0), "r"(a1), "r"(a2), "r"(a3), "r"(b0), "r"(b1));
}

__device__ __forceinline__ void ldsm_x4(uint32_t& r0, uint32_t& r1,
                                        uint32_t& r2, uint32_t& r3, uint32_t addr)
{
    asm volatile("ldmatrix.sync.aligned.m8n8.x4.shared.b16 {%0,%1,%2,%3}, [%4];"
        : "=r"(r0), "=r"(r1), "=r"(r2), "=r"(r3) : "r"(addr));
}

// ---------------------------------------------------------------------------
// fp16 GEMM: C[m][n] = scale * sum_k A[m][k] * B[n][k]   (A,B fp16; acc fp32)
// CTA 128(m) x 256(n), k-tile 32, 8 warps (2m x 4n), warp tile 64x64.
// 4-stage cp.async pipeline (3 in flight), ldmatrix fragment loads,
// 1 CTA/SM (acc-register ILP hides latency; CUTLASS-style shape).
// Smem row stride 80B: LDSM 8-row phases hit words {20r mod 32} = all banks.
// ---------------------------------------------------------------------------
#define TM 128
#define TN 256
#define KT 32
#define NST 4
#define ROWB 80                         // bytes per smem row (40 halfs)
#define A_BYTES (TM * ROWB)             // 10240
#define B_BYTES (TN * ROWB)             // 20480
#define STAGE   (A_BYTES + B_BYTES)     // 30720
#define GSMEM   (NST * STAGE)           // 122880

__device__ __forceinline__ void load_tile(uint32_t sst, const __half* __restrict__ Ab,
                                          const __half* __restrict__ Bb,
                                          int K, int ko, int tid)
{
    #pragma unroll
    for (int j = 0; j < 2; j++) {       // A: 128 rows x 4 uint4
        int i = tid + j * 256, row = i >> 2, q = i & 3;
        uint32_t dst = sst + row * ROWB + q * 16;
        const __half* src = Ab + (size_t)row * K + ko + q * 8;
        asm volatile("cp.async.cg.shared.global [%0], [%1], 16;\n" :: "r"(dst), "l"(src));
    }
    #pragma unroll
    for (int j = 0; j < 4; j++) {       // B: 256 rows x 4 uint4
        int i = tid + j * 256, row = i >> 2, q = i & 3;
        uint32_t dst = sst + A_BYTES + row * ROWB + q * 16;
        const __half* src = Bb + (size_t)row * K + ko + q * 8;
        asm volatile("cp.async.cg.shared.global [%0], [%1], 16;\n" :: "r"(dst), "l"(src));
    }
    asm volatile("cp.async.commit_group;\n");
}

template <bool HALF_OUT>
__global__ __launch_bounds__(256, 1) void gemm_h2(
    const __half* __restrict__ A, const __half* __restrict__ B, void* __restrict__ Cv,
    int Nglob, int K, size_t sA, size_t sB, size_t sC, float scale)
{
    extern __shared__ char sm[];
    uint32_t sbase = smem_u32(sm);
    int tid = threadIdx.x, lane = tid & 31, warp = tid >> 5;
    int r = lane >> 2, c = lane & 3;
    int wm = (warp >> 2) * 64;          // 0,64       (warp tile 64m x 64n)
    int wn = (warp & 3) * 64;           // 0,64,128,192

    const __half* Ab = A + blockIdx.z * sA + (size_t)(blockIdx.y * TM) * K;
    const __half* Bb = B + blockIdx.z * sB + (size_t)(blockIdx.x * TN) * K;
    int m0 = blockIdx.y * TM, n0 = blockIdx.x * TN;

    float acc[4][8][4] = {};            // [m-atom(16)][n-atom(8)][frag]

    // ldmatrix per-lane address components (within a stage)
    uint32_t a_off = (uint32_t)(wm + (lane & 15)) * ROWB + (lane >> 4) * 16;
    uint32_t b_off = A_BYTES
                   + (uint32_t)(wn + ((lane >> 4) * 8) + (lane & 7)) * ROWB
                   + ((lane >> 3) & 1) * 16;

    int nk = K / KT;
    load_tile(sbase + 0 * STAGE, Ab, Bb, K, 0 * KT, tid);
    load_tile(sbase + 1 * STAGE, Ab, Bb, K, 1 * KT, tid);
    load_tile(sbase + 2 * STAGE, Ab, Bb, K, 2 * KT, tid);

    for (int kt = 0; kt < nk; kt++) {
        int rem = nk - 1 - kt;
        if (rem >= 2)      asm volatile("cp.async.wait_group 2;\n" ::: "memory");
        else if (rem == 1) asm volatile("cp.async.wait_group 1;\n" ::: "memory");
        else               asm volatile("cp.async.wait_group 0;\n" ::: "memory");
        __syncthreads();

        if (kt + 3 < nk)
            load_tile(sbase + ((kt + 3) % NST) * STAGE, Ab, Bb, K, (kt + 3) * KT, tid);

        uint32_t st = sbase + (kt % NST) * STAGE;

        #pragma unroll
        for (int kk = 0; kk < 2; kk++) {
            uint32_t af[4][4], bf[8][2];
            uint32_t ab = st + a_off + kk * 32;
            #pragma unroll
            for (int ma = 0; ma < 4; ma++)
                ldsm_x4(af[ma][0], af[ma][1], af[ma][2], af[ma][3],
                        ab + ma * 16 * ROWB);
            uint32_t bb = st + b_off + kk * 32;
            #pragma unroll
            for (int p = 0; p < 4; p++)
                ldsm_x4(bf[2 * p][0], bf[2 * p][1], bf[2 * p + 1][0], bf[2 * p + 1][1],
                        bb + p * 16 * ROWB);
            #pragma unroll
            for (int ma = 0; ma < 4; ma++)
                #pragma unroll
                for (int na = 0; na < 8; na++)
                    mma_f16(acc[ma][na],
                            af[ma][0], af[ma][1], af[ma][2], af[ma][3],
                            bf[na][0], bf[na][1]);
        }
    }

    int cc = c * 2;
    #pragma unroll
    for (int ma = 0; ma < 4; ma++)
        #pragma unroll
        for (int na = 0; na < 8; na++) {
            int row = m0 + wm + ma * 16 + r;
            int col = n0 + wn + na * 8 + cc;
            float v0 = acc[ma][na][0] * scale, v1 = acc[ma][na][1] * scale;
            float v2 = acc[ma][na][2] * scale, v3 = acc[ma][na][3] * scale;
            if (HALF_OUT) {
                __half* Cb = (__half*)Cv + blockIdx.z * sC;
                *(__half2*)&Cb[(size_t)row * Nglob + col]       = __floats2half2_rn(v0, v1);
                *(__half2*)&Cb[(size_t)(row + 8) * Nglob + col] = __floats2half2_rn(v2, v3);
            } else {
                float* Cb = (float*)Cv + blockIdx.z * sC;
                *(float2*)&Cb[(size_t)row * Nglob + col]       = make_float2(v0, v1);
                *(float2*)&Cb[(size_t)(row + 8) * Nglob + col] = make_float2(v2, v3);
            }
        }
}

// ---------------------------------------------------------------------------
// x (B,C,N) f32 -> Xt (B,N,C) fp16
// ---------------------------------------------------------------------------
__global__ __launch_bounds__(256) void transpose_x(const float* __restrict__ x)
{
    __shared__ float tile[32][33];
    int b  = blockIdx.z;
    int t0 = blockIdx.x * 32;
    int c0 = blockIdx.y * 32;
    const float* in = x + (size_t)b * CC * NN;
    __half* out = g_Xth + (size_t)b * NN * CC;

    #pragma unroll
    for (int i = threadIdx.y; i < 32; i += 8)
        tile[i][threadIdx.x] = in[(size_t)(c0 + i) * NN + t0 + threadIdx.x];
    __syncthreads();
    #pragma unroll
    for (int i = threadIdx.y; i < 32; i += 8)
        out[(size_t)(t0 + i) * CC + c0 + threadIdx.x] = __float2half_rn(tile[threadIdx.x][i]);
}

__global__ __launch_bounds__(256) void conv_w(const float* __restrict__ Wq,
                                              const float* __restrict__ Wk,
                                              const float* __restrict__ Wv)
{
    int i = blockIdx.x * 256 + threadIdx.x;
    if (i < DD * CC) {
        g_Wqh[i] = __float2half_rn(Wq[i]);
        g_Wkh[i] = __float2half_rn(Wk[i]);
        g_Wvh[i] = __float2half_rn(Wv[i]);
    }
}

// ---------------------------------------------------------------------------
// Row softmax: read f32 S, write fp16 probs to g_Sh
// ---------------------------------------------------------------------------
__global__ __launch_bounds__(256) void softmax_kernel()
{
    __shared__ float red[256];
    size_t base = ((size_t)blockIdx.y * NN + blockIdx.x) * NN;
    const float* row = g_S + base;
    __half* rowh = g_Sh + base;
    int t = threadIdx.x;

    float vals[16];
    float m = -1e30f;
    #pragma unroll
    for (int u = 0; u < 16; u++) {
        vals[u] = row[t + u * 256];
        m = fmaxf(m, vals[u]);
    }
    red[t] = m;
    __syncthreads();
    for (int s = 128; s > 0; s >>= 1) {
        if (t < s) red[t] = fmaxf(red[t], red[t + s]);
        __syncthreads();
    }
    m = red[0];
    __syncthreads();

    float sum = 0.f;
    #pragma unroll
    for (int u = 0; u < 16; u++) {
        vals[u] = __expf(vals[u] - m);
        sum += vals[u];
    }
    red[t] = sum;
    __syncthreads();
    for (int s = 128; s > 0; s >>= 1) {
        if (t < s) red[t] += red[t + s];
        __syncthreads();
    }
    float inv = 1.0f / red[0];
    #pragma unroll
    for (int u = 0; u < 16; u++)
        rowh[t + u * 256] = __float2half_rn(vals[u] * inv);
}

// ---------------------------------------------------------------------------
// scores_out[b][j] = sum_i P[b][i][j] from fp16 probs
// ---------------------------------------------------------------------------
__global__ __launch_bounds__(256) void zero_scores(float* __restrict__ scores_out)
{
    int idx = blockIdx.x * 256 + threadIdx.x;
    if (idx < BB * NN) scores_out[idx] = 0.f;
}

__global__ __launch_bounds__(256) void colsum_kernel(float* __restrict__ scores_out)
{
    int b = blockIdx.z;
    int j = blockIdx.x * 256 + threadIdx.x;
    int i0 = blockIdx.y * 256;
    const __half* Sb = g_Sh + (size_t)b * NN * NN;
    float s = 0.f;
    #pragma unroll 8
    for (int i = i0; i < i0 + 256; i++)
        s += __half2float(Sb[(size_t)i * NN + j]);
    atomicAdd(&scores_out[(size_t)b * NN + j], s);
}

// ---------------------------------------------------------------------------
extern "C" void kernel_launch(void* const* d_in, const int* in_sizes, int n_in,
                              void* d_out, int out_size)
{
    const float* x  = (const float*)d_in[0];
    const float* Wk = (const float*)d_in[1];
    const float* Wq = (const float*)d_in[2];
    const float* Wv = (const float*)d_in[3];

    float* out        = (float*)d_out;                 // (B, D, H, W) = [b][d][t]
    float* scores_out = out + (size_t)BB * DD * NN;    // (B, 1, H, W)

    __half *Xt, *Q, *K, *Vt, *Sh, *Wqh, *Wkh, *Wvh;
    float *S;
    cudaGetSymbolAddress((void**)&Xt,  g_Xth);
    cudaGetSymbolAddress((void**)&Q,   g_Qh);
    cudaGetSymbolAddress((void**)&K,   g_Kh);
    cudaGetSymbolAddress((void**)&Vt,  g_Vth);
    cudaGetSymbolAddress((void**)&S,   g_S);
    cudaGetSymbolAddress((void**)&Sh,  g_Sh);
    cudaGetSymbolAddress((void**)&Wqh, g_Wqh);
    cudaGetSymbolAddress((void**)&Wkh, g_Wkh);
    cudaGetSymbolAddress((void**)&Wvh, g_Wvh);

    cudaFuncSetAttribute(gemm_h2<true>,  cudaFuncAttributeMaxDynamicSharedMemorySize, GSMEM);
    cudaFuncSetAttribute(gemm_h2<false>, cudaFuncAttributeMaxDynamicSharedMemorySize, GSMEM);

    // 0) fp16 operand prep
    conv_w<<<(DD * CC + 255) / 256, 256>>>(Wq, Wk, Wv);
    transpose_x<<<dim3(NN / 32, CC / 32, BB), dim3(32, 8)>>>(x);

    // 1) Q[t][d] = Xt . Wq^T
    gemm_h2<true><<<dim3(DD / TN, NN / TM, BB), 256, GSMEM>>>(
        Xt, Wqh, Q, DD, CC, (size_t)NN * CC, 0, (size_t)NN * DD, 1.0f);
    // 2) K[t][d] = Xt . Wk^T
    gemm_h2<true><<<dim3(DD / TN, NN / TM, BB), 256, GSMEM>>>(
        Xt, Wkh, K, DD, CC, (size_t)NN * CC, 0, (size_t)NN * DD, 1.0f);
    // 3) Vt[d][t] = Wv . Xt^T
    gemm_h2<true><<<dim3(NN / TN, DD / TM, BB), 256, GSMEM>>>(
        Wvh, Xt, Vt, NN, CC, 0, (size_t)NN * CC, (size_t)DD * NN, 1.0f);

    // 4) S[i][j] = SCALE * Q . K^T   (f32 out)
    gemm_h2<false><<<dim3(NN / TN, NN / TM, BB), 256, GSMEM>>>(
        Q, K, S, NN, DD, (size_t)NN * DD, (size_t)NN * DD, (size_t)NN * NN, SCALE);

    // 5) softmax rows -> fp16 probs
    softmax_kernel<<<dim3(NN, BB), 256>>>();

    // 6) out[d][t] = Vt . P^T  (f32 out, d-major layout directly)
    gemm_h2<false><<<dim3(NN / TN, DD / TM, BB), 256, GSMEM>>>(
        Vt, Sh, out, NN, NN, (size_t)DD * NN, (size_t)NN * NN, (size_t)DD * NN, 1.0f);

    // 7) scores_out[b][j] = sum_i P[b][i][j]
    zero_scores<<<(BB * NN + 255) / 256, 256>>>(scores_out);
    colsum_kernel<<<dim3(NN / 256, NN / 256, BB), 256>>>(scores_out);
}